// round 1
// baseline (speedup 1.0000x reference)
#include <cuda_runtime.h>
#include <cuda_bf16.h>
#include <math.h>

// Problem constants
#define BB 16
#define TT 256
#define EE 256
#define HH 512
#define G4H 2048
#define VV 32000
#define MROWS 4096           // B*T, row r = t*16 + b
#define NCTA_LSTM 128

// ------------------------- scratch (no mallocs allowed) -------------------------
__device__ float g_xw[(size_t)MROWS * G4H];     // 33.5 MB, reused for layer1/layer2
__device__ float g_h1[(size_t)MROWS * HH];      // 8 MB
__device__ float g_h2[(size_t)MROWS * HH];      // 8 MB
__device__ float g_hbuf[2 * BB * HH];           // ping-pong hidden state
__device__ unsigned g_bar_count;
__device__ unsigned g_bar_gen;

// ------------------------- global barrier (all CTAs resident) -------------------
__device__ __forceinline__ void grid_barrier(int ncta) {
    __syncthreads();
    if (threadIdx.x == 0) {
        __threadfence();
        unsigned gen = *(volatile unsigned*)&g_bar_gen;
        if (atomicAdd(&g_bar_count, 1u) == (unsigned)(ncta - 1)) {
            g_bar_count = 0;
            __threadfence();
            *(volatile unsigned*)&g_bar_gen = gen + 1u;
        } else {
            while (*(volatile unsigned*)&g_bar_gen == gen) { }
            __threadfence();
        }
    }
    __syncthreads();
}

// ------------------------- SGEMM 128x128 tile, 256 threads ----------------------
// MODE 0: A = emb gathered by tokens, C = g_xw        (M=4096,N=2048,K=256)
// MODE 1: A = g_h1,                   C = g_xw        (M=4096,N=2048,K=512)
// MODE 2: A = g_h2,                   C = d_out remap (M=4096,N=32000,K=512)
template<int MODE, int M, int N, int K>
__global__ __launch_bounds__(256, 2)
void sgemm_kernel(const float* __restrict__ Aparam,
                  const float* __restrict__ Bsrc,
                  const float* __restrict__ bias,
                  float* __restrict__ Cparam,
                  const int* __restrict__ tokens)
{
    __shared__ float As[16][128];
    __shared__ float Bs[16][128];

    const int tid = threadIdx.x;
    const int m0 = blockIdx.y * 128;
    const int n0 = blockIdx.x * 128;

    const float* Abase;
    if (MODE == 0)      Abase = Aparam;   // emb (gathered)
    else if (MODE == 1) Abase = g_h1;
    else                Abase = g_h2;
    float* Cdst = (MODE == 2) ? Cparam : g_xw;

    const int rg = (tid >> 4) * 4;   // row sub-group (0..60)
    const int cg = (tid & 15) * 4;   // col sub-group (0..60)

    float acc[8][8];
#pragma unroll
    for (int i = 0; i < 8; i++)
#pragma unroll
        for (int j = 0; j < 8; j++) acc[i][j] = 0.f;

    for (int kt = 0; kt < K; kt += 16) {
        __syncthreads();
        // load A tile: 128 rows x 16 k  (transposed into As[k][m])
#pragma unroll
        for (int it = 0; it < 2; it++) {
            int item = tid + it * 256;        // 0..511
            int m = item >> 2;
            int kq = item & 3;
            int gr = m0 + m;
            const float* arow;
            if (MODE == 0) {
                int tok = tokens[((gr & 15) << 8) + (gr >> 4)];
                arow = Abase + (size_t)tok * K;
            } else {
                arow = Abase + (size_t)gr * K;
            }
            float4 v = *(const float4*)(arow + kt + kq * 4);
            As[kq * 4 + 0][m] = v.x;
            As[kq * 4 + 1][m] = v.y;
            As[kq * 4 + 2][m] = v.z;
            As[kq * 4 + 3][m] = v.w;
        }
        // load B tile: 16 k x 128 n
#pragma unroll
        for (int it = 0; it < 2; it++) {
            int item = tid + it * 256;
            int k = item >> 5;
            int n4 = item & 31;
            float4 v = *(const float4*)(Bsrc + (size_t)(kt + k) * N + n0 + n4 * 4);
            *(float4*)&Bs[k][n4 * 4] = v;
        }
        __syncthreads();
#pragma unroll
        for (int kk = 0; kk < 16; kk++) {
            float4 a0 = *(const float4*)&As[kk][rg];
            float4 a1 = *(const float4*)&As[kk][64 + rg];
            float4 b0 = *(const float4*)&Bs[kk][cg];
            float4 b1 = *(const float4*)&Bs[kk][64 + cg];
            float a[8] = {a0.x, a0.y, a0.z, a0.w, a1.x, a1.y, a1.z, a1.w};
            float b[8] = {b0.x, b0.y, b0.z, b0.w, b1.x, b1.y, b1.z, b1.w};
#pragma unroll
            for (int i = 0; i < 8; i++)
#pragma unroll
                for (int j = 0; j < 8; j++)
                    acc[i][j] += a[i] * b[j];
        }
    }

    // epilogue: bias + (optional) row remap for logits layout [b][t][v]
    float bj[8];
#pragma unroll
    for (int j = 0; j < 4; j++) {
        bj[j]     = bias[n0 + cg + j];
        bj[4 + j] = bias[n0 + 64 + cg + j];
    }
#pragma unroll
    for (int i = 0; i < 8; i++) {
        int r = m0 + ((i < 4) ? (rg + i) : (64 + rg + i - 4));
        size_t outr;
        if (MODE == 2) outr = (size_t)((r & 15) * 256 + (r >> 4));
        else           outr = (size_t)r;
        float4 o0, o1;
        o0.x = acc[i][0] + bj[0]; o0.y = acc[i][1] + bj[1];
        o0.z = acc[i][2] + bj[2]; o0.w = acc[i][3] + bj[3];
        o1.x = acc[i][4] + bj[4]; o1.y = acc[i][5] + bj[5];
        o1.z = acc[i][6] + bj[6]; o1.w = acc[i][7] + bj[7];
        *(float4*)&Cdst[outr * N + n0 + cg]      = o0;
        *(float4*)&Cdst[outr * N + n0 + 64 + cg] = o1;
    }
}

// ------------------------- persistent LSTM recurrence ---------------------------
// 128 CTAs x 256 threads. CTA ct owns hidden units hu0..hu0+3 (hu0 = 4*ct),
// i.e. 16 gate columns {gate*512 + hu0 + j}. U slice lives in shared (padded).
// Thread (b = tid/16, lc = tid%16) computes z[b, gc(lc)] as a full 512-dot.
// layer: 0 -> write g_h1, 1 -> write g_h2.
__global__ __launch_bounds__(256, 1)
void lstm_kernel(const float* __restrict__ U, int layer)
{
    __shared__ float U_sh[16 * 516];   // stride 516 floats: conflict-free LDS.128
    __shared__ float z_sh[16][16];
    __shared__ float c_sh[16][4];

    const int tid = threadIdx.x;
    const int ct = blockIdx.x;
    const int hu0 = ct * 4;
    float* __restrict__ h_seq = layer ? g_h2 : g_h1;
    const float* __restrict__ xw = g_xw;

    // one-time preload of this CTA's 16 U columns
    for (int idx = tid; idx < 16 * 512; idx += 256) {
        int lc = idx >> 9;
        int k = idx & 511;
        int gc = ((lc >> 2) << 9) + hu0 + (lc & 3);
        U_sh[lc * 516 + k] = U[(size_t)k * G4H + gc];
    }
    if (tid < 64) c_sh[tid >> 2][tid & 3] = 0.f;
    __syncthreads();

    const int b = tid >> 4;
    const int lc = tid & 15;
    const int gc = ((lc >> 2) << 9) + hu0 + (lc & 3);
    const float* ucol = U_sh + lc * 516;

    for (int t = 0; t < TT; t++) {
        float acc = xw[((size_t)t * BB + b) * G4H + gc];
        if (t > 0) {
            const float* hprev = g_hbuf + ((t - 1) & 1) * (BB * HH) + b * HH;
            float a0 = 0.f, a1 = 0.f, a2 = 0.f, a3 = 0.f;
#pragma unroll 8
            for (int k = 0; k < HH; k += 4) {
                float4 h4 = *(const float4*)(hprev + k);
                float4 u4 = *(const float4*)(ucol + k);
                a0 += h4.x * u4.x;
                a1 += h4.y * u4.y;
                a2 += h4.z * u4.z;
                a3 += h4.w * u4.w;
            }
            acc += (a0 + a1) + (a2 + a3);
        }
        z_sh[b][lc] = acc;
        __syncthreads();
        if (tid < 64) {
            int bb = tid >> 2, j = tid & 3;
            float zi = z_sh[bb][j];
            float zf = z_sh[bb][4 + j];
            float zg = z_sh[bb][8 + j];
            float zo = z_sh[bb][12 + j];
            float ig = 1.f / (1.f + expf(-zi));
            float fg = 1.f / (1.f + expf(-zf));
            float gg = tanhf(zg);
            float og = 1.f / (1.f + expf(-zo));
            float c = fg * c_sh[bb][j] + ig * gg;
            c_sh[bb][j] = c;
            float h = og * tanhf(c);
            g_hbuf[(t & 1) * (BB * HH) + bb * HH + hu0 + j] = h;
            h_seq[((size_t)t * BB + bb) * HH + hu0 + j] = h;
            __threadfence();   // release this CTA's h slice before the barrier
        }
        grid_barrier(NCTA_LSTM);
    }
}

// ------------------------- launch -----------------------------------------------
extern "C" void kernel_launch(void* const* d_in, const int* in_sizes, int n_in,
                              void* d_out, int out_size)
{
    const int*   tokens = (const int*)  d_in[0];
    const float* emb    = (const float*)d_in[1];
    const float* W1     = (const float*)d_in[2];
    const float* U1     = (const float*)d_in[3];
    const float* b1     = (const float*)d_in[4];
    const float* W2     = (const float*)d_in[5];
    const float* U2     = (const float*)d_in[6];
    const float* b2     = (const float*)d_in[7];
    const float* Wd     = (const float*)d_in[8];
    const float* bd     = (const float*)d_in[9];
    float* out = (float*)d_out;

    // 1) xw1 = gather(emb, tokens) @ W1 + b1     rows r = t*16+b
    sgemm_kernel<0, MROWS, G4H, EE><<<dim3(G4H / 128, MROWS / 128), 256>>>(
        emb, W1, b1, nullptr, tokens);
    // 2) LSTM layer 1 -> g_h1
    lstm_kernel<<<NCTA_LSTM, 256>>>(U1, 0);
    // 3) xw2 = g_h1 @ W2 + b2
    sgemm_kernel<1, MROWS, G4H, HH><<<dim3(G4H / 128, MROWS / 128), 256>>>(
        nullptr, W2, b2, nullptr, nullptr);
    // 4) LSTM layer 2 -> g_h2
    lstm_kernel<<<NCTA_LSTM, 256>>>(U2, 1);
    // 5) logits = g_h2 @ Wd + bd  (with [t*16+b] -> [b*256+t] row remap)
    sgemm_kernel<2, MROWS, VV, HH><<<dim3(VV / 128, MROWS / 128), 256>>>(
        nullptr, Wd, bd, out, nullptr);
}

// round 3
// speedup vs baseline: 1.2237x; 1.2237x over previous
#include <cuda_runtime.h>
#include <cuda_bf16.h>
#include <math.h>
#include <stdint.h>

// Problem constants
#define BB 16
#define TT 256
#define EE 256
#define HH 512
#define G4H 2048
#define VV 32000
#define MROWS 4096           // B*T, row r = t*16 + b
#define NCTA_LSTM 128

// ------------------------- scratch (no mallocs allowed) -------------------------
__device__ float g_xw[(size_t)MROWS * G4H];     // 33.5 MB, reused for layer1/layer2
__device__ float g_h1[(size_t)MROWS * HH];      // 8 MB
__device__ float g_h2[(size_t)MROWS * HH];      // 8 MB
__device__ float g_hbuf[2 * BB * HH];           // ping-pong hidden state
__device__ unsigned g_bar_count;
__device__ unsigned g_bar_gen;

// bf16 hi/lo split operands for the tensor-core dense layer
__device__ __nv_bfloat16 g_a_hi[(size_t)MROWS * HH];
__device__ __nv_bfloat16 g_a_lo[(size_t)MROWS * HH];
__device__ __nv_bfloat16 g_b_hi[(size_t)VV * HH];   // [v][h], transposed Wd
__device__ __nv_bfloat16 g_b_lo[(size_t)VV * HH];

// ------------------------- global barrier (all CTAs resident) -------------------
__device__ __forceinline__ void grid_barrier(int ncta) {
    __syncthreads();
    if (threadIdx.x == 0) {
        __threadfence();
        unsigned gen = *(volatile unsigned*)&g_bar_gen;
        if (atomicAdd(&g_bar_count, 1u) == (unsigned)(ncta - 1)) {
            g_bar_count = 0;
            __threadfence();
            *(volatile unsigned*)&g_bar_gen = gen + 1u;
        } else {
            while (*(volatile unsigned*)&g_bar_gen == gen) { }
            __threadfence();
        }
    }
    __syncthreads();
}

// ------------------------- SGEMM 128x128 tile, 256 threads (fp32, small GEMMs) --
// MODE 0: A = emb gathered by tokens, C = g_xw        (M=4096,N=2048,K=256)
// MODE 1: A = g_h1,                   C = g_xw        (M=4096,N=2048,K=512)
template<int MODE, int M, int N, int K>
__global__ __launch_bounds__(256, 2)
void sgemm_kernel(const float* __restrict__ Aparam,
                  const float* __restrict__ Bsrc,
                  const float* __restrict__ bias,
                  float* __restrict__ Cparam,
                  const int* __restrict__ tokens)
{
    __shared__ float As[16][128];
    __shared__ float Bs[16][128];

    const int tid = threadIdx.x;
    const int m0 = blockIdx.y * 128;
    const int n0 = blockIdx.x * 128;

    const float* Abase;
    if (MODE == 0)      Abase = Aparam;   // emb (gathered)
    else                Abase = g_h1;
    float* Cdst = g_xw;

    const int rg = (tid >> 4) * 4;
    const int cg = (tid & 15) * 4;

    float acc[8][8];
#pragma unroll
    for (int i = 0; i < 8; i++)
#pragma unroll
        for (int j = 0; j < 8; j++) acc[i][j] = 0.f;

    for (int kt = 0; kt < K; kt += 16) {
        __syncthreads();
#pragma unroll
        for (int it = 0; it < 2; it++) {
            int item = tid + it * 256;
            int m = item >> 2;
            int kq = item & 3;
            int gr = m0 + m;
            const float* arow;
            if (MODE == 0) {
                int tok = tokens[((gr & 15) << 8) + (gr >> 4)];
                arow = Abase + (size_t)tok * K;
            } else {
                arow = Abase + (size_t)gr * K;
            }
            float4 v = *(const float4*)(arow + kt + kq * 4);
            As[kq * 4 + 0][m] = v.x;
            As[kq * 4 + 1][m] = v.y;
            As[kq * 4 + 2][m] = v.z;
            As[kq * 4 + 3][m] = v.w;
        }
#pragma unroll
        for (int it = 0; it < 2; it++) {
            int item = tid + it * 256;
            int k = item >> 5;
            int n4 = item & 31;
            float4 v = *(const float4*)(Bsrc + (size_t)(kt + k) * N + n0 + n4 * 4);
            *(float4*)&Bs[k][n4 * 4] = v;
        }
        __syncthreads();
#pragma unroll
        for (int kk = 0; kk < 16; kk++) {
            float4 a0 = *(const float4*)&As[kk][rg];
            float4 a1 = *(const float4*)&As[kk][64 + rg];
            float4 b0 = *(const float4*)&Bs[kk][cg];
            float4 b1 = *(const float4*)&Bs[kk][64 + cg];
            float a[8] = {a0.x, a0.y, a0.z, a0.w, a1.x, a1.y, a1.z, a1.w};
            float b[8] = {b0.x, b0.y, b0.z, b0.w, b1.x, b1.y, b1.z, b1.w};
#pragma unroll
            for (int i = 0; i < 8; i++)
#pragma unroll
                for (int j = 0; j < 8; j++)
                    acc[i][j] += a[i] * b[j];
        }
    }

    float bj[8];
#pragma unroll
    for (int j = 0; j < 4; j++) {
        bj[j]     = bias[n0 + cg + j];
        bj[4 + j] = bias[n0 + 64 + cg + j];
    }
#pragma unroll
    for (int i = 0; i < 8; i++) {
        int r = m0 + ((i < 4) ? (rg + i) : (64 + rg + i - 4));
        size_t outr = (size_t)r;
        float4 o0, o1;
        o0.x = acc[i][0] + bj[0]; o0.y = acc[i][1] + bj[1];
        o0.z = acc[i][2] + bj[2]; o0.w = acc[i][3] + bj[3];
        o1.x = acc[i][4] + bj[4]; o1.y = acc[i][5] + bj[5];
        o1.z = acc[i][6] + bj[6]; o1.w = acc[i][7] + bj[7];
        *(float4*)&Cdst[outr * N + n0 + cg]      = o0;
        *(float4*)&Cdst[outr * N + n0 + 64 + cg] = o1;
    }
}

// ------------------------- persistent LSTM recurrence ---------------------------
__global__ __launch_bounds__(256, 1)
void lstm_kernel(const float* __restrict__ U, int layer)
{
    __shared__ float U_sh[16 * 516];
    __shared__ float z_sh[16][16];
    __shared__ float c_sh[16][4];

    const int tid = threadIdx.x;
    const int ct = blockIdx.x;
    const int hu0 = ct * 4;
    float* __restrict__ h_seq = layer ? g_h2 : g_h1;
    const float* __restrict__ xw = g_xw;

    for (int idx = tid; idx < 16 * 512; idx += 256) {
        int lc = idx >> 9;
        int k = idx & 511;
        int gc = ((lc >> 2) << 9) + hu0 + (lc & 3);
        U_sh[lc * 516 + k] = U[(size_t)k * G4H + gc];
    }
    if (tid < 64) c_sh[tid >> 2][tid & 3] = 0.f;
    __syncthreads();

    const int b = tid >> 4;
    const int lc = tid & 15;
    const int gc = ((lc >> 2) << 9) + hu0 + (lc & 3);
    const float* ucol = U_sh + lc * 516;

    for (int t = 0; t < TT; t++) {
        float acc = xw[((size_t)t * BB + b) * G4H + gc];
        if (t > 0) {
            const float* hprev = g_hbuf + ((t - 1) & 1) * (BB * HH) + b * HH;
            float a0 = 0.f, a1 = 0.f, a2 = 0.f, a3 = 0.f;
#pragma unroll 8
            for (int k = 0; k < HH; k += 4) {
                float4 h4 = *(const float4*)(hprev + k);
                float4 u4 = *(const float4*)(ucol + k);
                a0 += h4.x * u4.x;
                a1 += h4.y * u4.y;
                a2 += h4.z * u4.z;
                a3 += h4.w * u4.w;
            }
            acc += (a0 + a1) + (a2 + a3);
        }
        z_sh[b][lc] = acc;
        __syncthreads();
        if (tid < 64) {
            int bb = tid >> 2, j = tid & 3;
            float zi = z_sh[bb][j];
            float zf = z_sh[bb][4 + j];
            float zg = z_sh[bb][8 + j];
            float zo = z_sh[bb][12 + j];
            float ig = 1.f / (1.f + expf(-zi));
            float fg = 1.f / (1.f + expf(-zf));
            float gg = tanhf(zg);
            float og = 1.f / (1.f + expf(-zo));
            float c = fg * c_sh[bb][j] + ig * gg;
            c_sh[bb][j] = c;
            float h = og * tanhf(c);
            g_hbuf[(t & 1) * (BB * HH) + bb * HH + hu0 + j] = h;
            h_seq[((size_t)t * BB + bb) * HH + hu0 + j] = h;
            __threadfence();
        }
        grid_barrier(NCTA_LSTM);
    }
}

// ------------------------- bf16 split conversion kernels ------------------------
__global__ void splitA_kernel()
{
    int i = (blockIdx.x * blockDim.x + threadIdx.x) * 4;
    float4 x = *(const float4*)(g_h2 + i);
    __nv_bfloat16 h0 = __float2bfloat16(x.x);
    __nv_bfloat16 h1 = __float2bfloat16(x.y);
    __nv_bfloat16 h2 = __float2bfloat16(x.z);
    __nv_bfloat16 h3 = __float2bfloat16(x.w);
    g_a_hi[i + 0] = h0; g_a_lo[i + 0] = __float2bfloat16(x.x - __bfloat162float(h0));
    g_a_hi[i + 1] = h1; g_a_lo[i + 1] = __float2bfloat16(x.y - __bfloat162float(h1));
    g_a_hi[i + 2] = h2; g_a_lo[i + 2] = __float2bfloat16(x.z - __bfloat162float(h2));
    g_a_hi[i + 3] = h3; g_a_lo[i + 3] = __float2bfloat16(x.w - __bfloat162float(h3));
}

// Wd [512][32000] fp32 -> g_b_hi/lo [32000][512] bf16 (tiled transpose)
__global__ void transB_kernel(const float* __restrict__ Wd)
{
    __shared__ __nv_bfloat16 shi[32][33];
    __shared__ __nv_bfloat16 slo[32][33];
    const int v0 = blockIdx.x * 32;
    const int h0 = blockIdx.y * 32;
    const int tx = threadIdx.x;
    const int ty = threadIdx.y;
#pragma unroll
    for (int j = 0; j < 4; j++) {
        int hr = ty + j * 8;
        float x = Wd[(size_t)(h0 + hr) * VV + v0 + tx];
        __nv_bfloat16 hi = __float2bfloat16(x);
        shi[hr][tx] = hi;
        slo[hr][tx] = __float2bfloat16(x - __bfloat162float(hi));
    }
    __syncthreads();
#pragma unroll
    for (int j = 0; j < 4; j++) {
        int vr = ty + j * 8;
        size_t o = (size_t)(v0 + vr) * HH + h0 + tx;
        g_b_hi[o] = shi[tx][vr];
        g_b_lo[o] = slo[tx][vr];
    }
}

// ------------------------- HMMA dense GEMM (bf16 split, mma.sync) ---------------
// C[4096, 32000] = h2 @ Wd^T + bd. CTA tile 128x128, warp tile 64x32.
// K=512 in 16 chunks of 32, double-buffered via cp.async.
// smem per stage: A_hi | A_lo | B_hi | B_lo, each 128 rows x 32 bf16, row stride 40.
#define DROW 40              // padded row stride in bf16 elements (80 bytes)
#define DARR 10240u          // bytes per sub-array (128*80)
#define DSTG 40960u          // bytes per stage (4 arrays)

__device__ __forceinline__ uint32_t smem_u32(const void* p) {
    uint32_t a;
    asm("{ .reg .u64 t; cvta.to.shared.u64 t, %1; cvt.u32.u64 %0, t; }" : "=r"(a) : "l"(p));
    return a;
}
__device__ __forceinline__ void cp_async16(uint32_t saddr, const void* gptr) {
    asm volatile("cp.async.cg.shared.global [%0], [%1], 16;"
                 :: "r"(saddr), "l"(__cvta_generic_to_global(gptr)) : "memory");
}
__device__ __forceinline__ void cp_commit() {
    asm volatile("cp.async.commit_group;" ::: "memory");
}
template<int N>
__device__ __forceinline__ void cp_wait() {
    asm volatile("cp.async.wait_group %0;" :: "n"(N) : "memory");
}
__device__ __forceinline__ void ldm_x4(uint32_t* r, uint32_t a) {
    asm volatile("ldmatrix.sync.aligned.m8n8.x4.shared.b16 {%0,%1,%2,%3}, [%4];"
                 : "=r"(r[0]), "=r"(r[1]), "=r"(r[2]), "=r"(r[3]) : "r"(a));
}
__device__ __forceinline__ void mma_bf16(float* d, const uint32_t* a, uint32_t b0, uint32_t b1) {
    asm volatile(
        "mma.sync.aligned.m16n8k16.row.col.f32.bf16.bf16.f32 "
        "{%0,%1,%2,%3}, {%4,%5,%6,%7}, {%8,%9}, {%0,%1,%2,%3};"
        : "+f"(d[0]), "+f"(d[1]), "+f"(d[2]), "+f"(d[3])
        : "r"(a[0]), "r"(a[1]), "r"(a[2]), "r"(a[3]), "r"(b0), "r"(b1));
}

__device__ __forceinline__ void dense_load_chunk(uint32_t sb, int m0, int n0, int c, int tid)
{
    const uint32_t stg = sb + (uint32_t)(c & 1) * DSTG;
    const int kc0 = c * 32;
#pragma unroll
    for (int it = 0; it < 8; it++) {
        int u = tid + it * 256;          // 0..2047 16B units
        int arr = u >> 9;                // 0 A_hi, 1 A_lo, 2 B_hi, 3 B_lo
        int u2 = u & 511;
        int r = u2 >> 2, q = u2 & 3;
        const __nv_bfloat16* g;
        int grow;
        if (arr == 0)      { g = g_a_hi; grow = m0; }
        else if (arr == 1) { g = g_a_lo; grow = m0; }
        else if (arr == 2) { g = g_b_hi; grow = n0; }
        else               { g = g_b_lo; grow = n0; }
        cp_async16(stg + (uint32_t)arr * DARR + (uint32_t)(r * 80 + q * 16),
                   g + (size_t)(grow + r) * HH + kc0 + q * 8);
    }
    cp_commit();
}

__global__ __launch_bounds__(256, 2)
void dense_kernel(const float* __restrict__ bd, float* __restrict__ out)
{
    extern __shared__ char smem[];
    const uint32_t sb = smem_u32(smem);
    const int tid = threadIdx.x;
    const int wid = tid >> 5;
    const int lane = tid & 31;
    const int n0 = blockIdx.x * 128;
    const int m0 = blockIdx.y * 128;
    const int wm = wid & 1;              // 2 warps along M (64 rows each)
    const int wn = wid >> 1;             // 4 warps along N (32 cols each)
    const int lrow = lane & 15;
    const int lsel = (lane >> 4) << 4;   // 0 or 16 bytes (k half)

    float acc[4][4][4];                  // [mt][nt][4]
#pragma unroll
    for (int mt = 0; mt < 4; mt++)
#pragma unroll
        for (int nt = 0; nt < 4; nt++)
#pragma unroll
            for (int e = 0; e < 4; e++) acc[mt][nt][e] = 0.f;

    dense_load_chunk(sb, m0, n0, 0, tid);

    for (int c = 0; c < 16; c++) {
        if (c < 15) {
            dense_load_chunk(sb, m0, n0, c + 1, tid);
            cp_wait<1>();
        } else {
            cp_wait<0>();
        }
        __syncthreads();
        const uint32_t stg = sb + (uint32_t)(c & 1) * DSTG;
        const uint32_t a_hi_b = stg + (uint32_t)((wm * 64 + lrow) * 80) + lsel;
        const uint32_t b_hi_b = stg + 2u * DARR + (uint32_t)((wn * 32 + lrow) * 80) + lsel;
#pragma unroll
        for (int s = 0; s < 2; s++) {
            uint32_t bhi[2][4], blo[2][4];
#pragma unroll
            for (int i = 0; i < 2; i++) {
                ldm_x4(bhi[i], b_hi_b + (uint32_t)(i * 16 * 80 + s * 32));
                ldm_x4(blo[i], b_hi_b + DARR + (uint32_t)(i * 16 * 80 + s * 32));
            }
#pragma unroll
            for (int mt = 0; mt < 4; mt++) {
                uint32_t a[4];
                uint32_t abase = a_hi_b + (uint32_t)(mt * 16 * 80 + s * 32);
                ldm_x4(a, abase);                          // A_hi
#pragma unroll
                for (int nt = 0; nt < 4; nt++) {           // hi*hi
                    uint32_t b0 = bhi[nt >> 1][nt & 1];
                    uint32_t b1 = bhi[nt >> 1][(nt & 1) + 2];
                    mma_bf16(acc[mt][nt], a, b0, b1);
                }
#pragma unroll
                for (int nt = 0; nt < 4; nt++) {           // hi*lo
                    uint32_t b0 = blo[nt >> 1][nt & 1];
                    uint32_t b1 = blo[nt >> 1][(nt & 1) + 2];
                    mma_bf16(acc[mt][nt], a, b0, b1);
                }
                ldm_x4(a, abase + DARR);                   // A_lo
#pragma unroll
                for (int nt = 0; nt < 4; nt++) {           // lo*hi
                    uint32_t b0 = bhi[nt >> 1][nt & 1];
                    uint32_t b1 = bhi[nt >> 1][(nt & 1) + 2];
                    mma_bf16(acc[mt][nt], a, b0, b1);
                }
            }
        }
        __syncthreads();
    }

    // epilogue: direct stores (32B sector-aligned segments) with row remap
    const int g = lane >> 2;
    const int tig = lane & 3;
#pragma unroll
    for (int nt = 0; nt < 4; nt++) {
        int col = n0 + wn * 32 + nt * 8 + tig * 2;
        float b0 = __ldg(bd + col);
        float b1 = __ldg(bd + col + 1);
#pragma unroll
        for (int mt = 0; mt < 4; mt++) {
            int r0 = m0 + wm * 64 + mt * 16 + g;
            int r1 = r0 + 8;
            size_t o0 = (size_t)((r0 & 15) * 256 + (r0 >> 4));
            size_t o1 = (size_t)((r1 & 15) * 256 + (r1 >> 4));
            float2 v0 = make_float2(acc[mt][nt][0] + b0, acc[mt][nt][1] + b1);
            float2 v1 = make_float2(acc[mt][nt][2] + b0, acc[mt][nt][3] + b1);
            *(float2*)(out + o0 * VV + col) = v0;
            *(float2*)(out + o1 * VV + col) = v1;
        }
    }
}

// ------------------------- launch -----------------------------------------------
extern "C" void kernel_launch(void* const* d_in, const int* in_sizes, int n_in,
                              void* d_out, int out_size)
{
    const int*   tokens = (const int*)  d_in[0];
    const float* emb    = (const float*)d_in[1];
    const float* W1     = (const float*)d_in[2];
    const float* U1     = (const float*)d_in[3];
    const float* b1     = (const float*)d_in[4];
    const float* W2     = (const float*)d_in[5];
    const float* U2     = (const float*)d_in[6];
    const float* b2     = (const float*)d_in[7];
    const float* Wd     = (const float*)d_in[8];
    const float* bd     = (const float*)d_in[9];
    float* out = (float*)d_out;

    cudaFuncSetAttribute(dense_kernel, cudaFuncAttributeMaxDynamicSharedMemorySize,
                         (int)(2 * DSTG));

    // B split/transpose is independent of everything else — do it first
    transB_kernel<<<dim3(VV / 32, HH / 32), dim3(32, 8)>>>(Wd);
    // 1) xw1 = gather(emb, tokens) @ W1 + b1     rows r = t*16+b
    sgemm_kernel<0, MROWS, G4H, EE><<<dim3(G4H / 128, MROWS / 128), 256>>>(
        emb, W1, b1, nullptr, tokens);
    // 2) LSTM layer 1 -> g_h1
    lstm_kernel<<<NCTA_LSTM, 256>>>(U1, 0);
    // 3) xw2 = g_h1 @ W2 + b2
    sgemm_kernel<1, MROWS, G4H, HH><<<dim3(G4H / 128, MROWS / 128), 256>>>(
        nullptr, W2, b2, nullptr, nullptr);
    // 4) LSTM layer 2 -> g_h2
    lstm_kernel<<<NCTA_LSTM, 256>>>(U2, 1);
    // 5) split h2 into bf16 hi/lo
    splitA_kernel<<<(MROWS * HH) / (256 * 4), 256>>>();
    // 6) logits = h2 @ Wd + bd on HMMA tensor cores (bf16 hi/lo x3), remap in epilogue
    dense_kernel<<<dim3(VV / 128, MROWS / 128), 256, 2 * DSTG>>>(bd, out);
}

// round 4
// speedup vs baseline: 2.2474x; 1.8365x over previous
#include <cuda_runtime.h>
#include <cuda_bf16.h>
#include <cuda_fp16.h>
#include <math.h>
#include <stdint.h>

// Problem constants
#define BB 16
#define TT 256
#define EE 256
#define HH 512
#define G4H 2048
#define VV 32000
#define MROWS 4096           // B*T, row r = t*16 + b
#define NCTA_LSTM 128

// ------------------------- scratch (no mallocs allowed) -------------------------
__device__ float g_xw[(size_t)MROWS * G4H];     // 33.5 MB, reused for layer1/layer2
__device__ float g_h1[(size_t)MROWS * HH];      // 8 MB
__device__ float g_h2[(size_t)MROWS * HH];      // 8 MB
__device__ float g_hbuf[2 * BB * HH];           // ping-pong hidden state
__device__ unsigned g_bar_count;
__device__ unsigned g_bar_gen;

// fp16 operands for the tensor-core dense layer
__device__ __half g_a_h[(size_t)MROWS * HH];    // 4 MB
__device__ __half g_b_h[(size_t)VV * HH];       // 32.8 MB, [v][h] transposed Wd

// ------------------------- small PTX helpers ------------------------------------
__device__ __forceinline__ uint32_t smem_u32(const void* p) {
    uint32_t a;
    asm("{ .reg .u64 t; cvta.to.shared.u64 t, %1; cvt.u32.u64 %0, t; }" : "=r"(a) : "l"(p));
    return a;
}
__device__ __forceinline__ void cp_async16(uint32_t saddr, const void* gptr) {
    asm volatile("cp.async.cg.shared.global [%0], [%1], 16;"
                 :: "r"(saddr), "l"(__cvta_generic_to_global(gptr)) : "memory");
}
__device__ __forceinline__ void cp_commit() {
    asm volatile("cp.async.commit_group;" ::: "memory");
}
template<int N>
__device__ __forceinline__ void cp_wait() {
    asm volatile("cp.async.wait_group %0;" :: "n"(N) : "memory");
}
__device__ __forceinline__ void ldm_x4(uint32_t* r, uint32_t a) {
    asm volatile("ldmatrix.sync.aligned.m8n8.x4.shared.b16 {%0,%1,%2,%3}, [%4];"
                 : "=r"(r[0]), "=r"(r[1]), "=r"(r[2]), "=r"(r[3]) : "r"(a));
}
__device__ __forceinline__ void mma_f16(float* d, const uint32_t* a, uint32_t b0, uint32_t b1) {
    asm volatile(
        "mma.sync.aligned.m16n8k16.row.col.f32.f16.f16.f32 "
        "{%0,%1,%2,%3}, {%4,%5,%6,%7}, {%8,%9}, {%0,%1,%2,%3};"
        : "+f"(d[0]), "+f"(d[1]), "+f"(d[2]), "+f"(d[3])
        : "r"(a[0]), "r"(a[1]), "r"(a[2]), "r"(a[3]), "r"(b0), "r"(b1));
}

// ------------------------- global barrier (all CTAs resident) -------------------
__device__ __forceinline__ void grid_barrier(int ncta) {
    __syncthreads();
    if (threadIdx.x == 0) {
        __threadfence();
        unsigned gen = *(volatile unsigned*)&g_bar_gen;
        if (atomicAdd(&g_bar_count, 1u) == (unsigned)(ncta - 1)) {
            g_bar_count = 0;
            __threadfence();
            *(volatile unsigned*)&g_bar_gen = gen + 1u;
        } else {
            while (*(volatile unsigned*)&g_bar_gen == gen) { }
            __threadfence();
        }
    }
    __syncthreads();
}

// ------------------------- SGEMM 128x128 tile, 256 threads (fp32, small GEMMs) --
// MODE 0: A = emb gathered by tokens, C = g_xw        (M=4096,N=2048,K=256)
// MODE 1: A = g_h1,                   C = g_xw        (M=4096,N=2048,K=512)
template<int MODE, int M, int N, int K>
__global__ __launch_bounds__(256, 2)
void sgemm_kernel(const float* __restrict__ Aparam,
                  const float* __restrict__ Bsrc,
                  const float* __restrict__ bias,
                  float* __restrict__ Cparam,
                  const int* __restrict__ tokens)
{
    __shared__ float As[16][128];
    __shared__ float Bs[16][128];

    const int tid = threadIdx.x;
    const int m0 = blockIdx.y * 128;
    const int n0 = blockIdx.x * 128;

    const float* Abase;
    if (MODE == 0)      Abase = Aparam;   // emb (gathered)
    else                Abase = g_h1;
    float* Cdst = g_xw;

    const int rg = (tid >> 4) * 4;
    const int cg = (tid & 15) * 4;

    float acc[8][8];
#pragma unroll
    for (int i = 0; i < 8; i++)
#pragma unroll
        for (int j = 0; j < 8; j++) acc[i][j] = 0.f;

    for (int kt = 0; kt < K; kt += 16) {
        __syncthreads();
#pragma unroll
        for (int it = 0; it < 2; it++) {
            int item = tid + it * 256;
            int m = item >> 2;
            int kq = item & 3;
            int gr = m0 + m;
            const float* arow;
            if (MODE == 0) {
                int tok = tokens[((gr & 15) << 8) + (gr >> 4)];
                arow = Abase + (size_t)tok * K;
            } else {
                arow = Abase + (size_t)gr * K;
            }
            float4 v = *(const float4*)(arow + kt + kq * 4);
            As[kq * 4 + 0][m] = v.x;
            As[kq * 4 + 1][m] = v.y;
            As[kq * 4 + 2][m] = v.z;
            As[kq * 4 + 3][m] = v.w;
        }
#pragma unroll
        for (int it = 0; it < 2; it++) {
            int item = tid + it * 256;
            int k = item >> 5;
            int n4 = item & 31;
            float4 v = *(const float4*)(Bsrc + (size_t)(kt + k) * N + n0 + n4 * 4);
            *(float4*)&Bs[k][n4 * 4] = v;
        }
        __syncthreads();
#pragma unroll
        for (int kk = 0; kk < 16; kk++) {
            float4 a0 = *(const float4*)&As[kk][rg];
            float4 a1 = *(const float4*)&As[kk][64 + rg];
            float4 b0 = *(const float4*)&Bs[kk][cg];
            float4 b1 = *(const float4*)&Bs[kk][64 + cg];
            float a[8] = {a0.x, a0.y, a0.z, a0.w, a1.x, a1.y, a1.z, a1.w};
            float b[8] = {b0.x, b0.y, b0.z, b0.w, b1.x, b1.y, b1.z, b1.w};
#pragma unroll
            for (int i = 0; i < 8; i++)
#pragma unroll
                for (int j = 0; j < 8; j++)
                    acc[i][j] += a[i] * b[j];
        }
    }

    float bj[8];
#pragma unroll
    for (int j = 0; j < 4; j++) {
        bj[j]     = bias[n0 + cg + j];
        bj[4 + j] = bias[n0 + 64 + cg + j];
    }
#pragma unroll
    for (int i = 0; i < 8; i++) {
        int r = m0 + ((i < 4) ? (rg + i) : (64 + rg + i - 4));
        size_t outr = (size_t)r;
        float4 o0, o1;
        o0.x = acc[i][0] + bj[0]; o0.y = acc[i][1] + bj[1];
        o0.z = acc[i][2] + bj[2]; o0.w = acc[i][3] + bj[3];
        o1.x = acc[i][4] + bj[4]; o1.y = acc[i][5] + bj[5];
        o1.z = acc[i][6] + bj[6]; o1.w = acc[i][7] + bj[7];
        *(float4*)&Cdst[outr * N + n0 + cg]      = o0;
        *(float4*)&Cdst[outr * N + n0 + 64 + cg] = o1;
    }
}

// ------------------------- persistent LSTM recurrence (register-cached U) -------
// 128 CTAs x 256 threads. CTA ct owns 4 hidden units (16 gate cols).
// Thread (ks = tid/16, lc = tid%16): holds U[ks*32 .. ks*32+31][gc(lc)] in regs.
// Per step: stage hprev (16x512 f32, 32KB) into smem via cp.async, each thread
// does 16 b x 32 k partial dots from registers + broadcast LDS, reduce via smem.
__global__ __launch_bounds__(256, 1)
void lstm_kernel(const float* __restrict__ U, int layer)
{
    __shared__ float h_sh[BB * HH];          // 32 KB
    __shared__ float part[16][16][16];       // [b][ks][lc] 16 KB
    __shared__ float zsh[16][16];
    __shared__ float c_sh[16][4];

    const int tid = threadIdx.x;
    const int ct = blockIdx.x;
    const int hu0 = ct * 4;
    const int ks = tid >> 4;
    const int lc = tid & 15;
    const int gcg = ((lc >> 2) << 9) + hu0 + (lc & 3);
    float* __restrict__ h_seq = layer ? g_h2 : g_h1;
    const uint32_t h_sh_addr = smem_u32(h_sh);

    // one-time: cache this thread's 32 U values in registers
    float u[32];
#pragma unroll
    for (int j = 0; j < 32; j++)
        u[j] = U[(size_t)(ks * 32 + j) * G4H + gcg];
    if (tid < 64) c_sh[tid >> 2][tid & 3] = 0.f;
    __syncthreads();

    for (int t = 0; t < TT; t++) {
        // xw contribution for this thread's (b=ks, gc=lc) reduction role
        float xwv = __ldg(&g_xw[((size_t)t * BB + ks) * G4H + gcg]);

        if (t > 0) {
            // stage hprev into shared (32KB, 8 x 16B per thread)
            const float* hp = g_hbuf + ((t - 1) & 1) * (BB * HH);
#pragma unroll
            for (int i = 0; i < 8; i++) {
                int idx = tid + i * 256;         // 16B units
                cp_async16(h_sh_addr + (uint32_t)idx * 16u, hp + idx * 4);
            }
            cp_commit();
            cp_wait<0>();
            __syncthreads();

            // partial dots: 16 b x 32 k from registers
            const float4* hrow4 = (const float4*)h_sh;
#pragma unroll 4
            for (int b = 0; b < 16; b++) {
                float a0 = 0.f, a1 = 0.f, a2 = 0.f, a3 = 0.f;
#pragma unroll
                for (int j4 = 0; j4 < 8; j4++) {
                    float4 h4 = hrow4[b * 128 + ks * 8 + j4];   // broadcast LDS.128
                    a0 += h4.x * u[j4 * 4 + 0];
                    a1 += h4.y * u[j4 * 4 + 1];
                    a2 += h4.z * u[j4 * 4 + 2];
                    a3 += h4.w * u[j4 * 4 + 3];
                }
                part[b][ks][lc] = (a0 + a1) + (a2 + a3);
            }
            __syncthreads();
        }

        // reduce over ks for (b=ks, lc)
        float z = xwv;
        if (t > 0) {
#pragma unroll
            for (int k = 0; k < 16; k++) z += part[ks][k][lc];
        }
        zsh[ks][lc] = z;
        __syncthreads();

        if (tid < 64) {
            int bb = tid >> 2, j = tid & 3;
            float zi = zsh[bb][j];
            float zf = zsh[bb][4 + j];
            float zg = zsh[bb][8 + j];
            float zo = zsh[bb][12 + j];
            float ig = 1.f / (1.f + expf(-zi));
            float fg = 1.f / (1.f + expf(-zf));
            float gg = tanhf(zg);
            float og = 1.f / (1.f + expf(-zo));
            float c = fg * c_sh[bb][j] + ig * gg;
            c_sh[bb][j] = c;
            float h = og * tanhf(c);
            g_hbuf[(t & 1) * (BB * HH) + bb * HH + hu0 + j] = h;
            h_seq[((size_t)t * BB + bb) * HH + hu0 + j] = h;
            __threadfence();
        }
        grid_barrier(NCTA_LSTM);
    }
}

// ------------------------- fp16 conversion kernels ------------------------------
__global__ void convA_kernel()
{
    int i = (blockIdx.x * blockDim.x + threadIdx.x) * 4;
    float4 x = *(const float4*)(g_h2 + i);
    g_a_h[i + 0] = __float2half(x.x);
    g_a_h[i + 1] = __float2half(x.y);
    g_a_h[i + 2] = __float2half(x.z);
    g_a_h[i + 3] = __float2half(x.w);
}

// Wd [512][32000] fp32 -> g_b_h [32000][512] fp16 (tiled transpose)
__global__ void transB_kernel(const float* __restrict__ Wd)
{
    __shared__ __half sh[32][33];
    const int v0 = blockIdx.x * 32;
    const int h0 = blockIdx.y * 32;
    const int tx = threadIdx.x;   // 0..31
    const int ty = threadIdx.y;   // 0..7
#pragma unroll
    for (int j = 0; j < 4; j++) {
        int hr = ty + j * 8;
        sh[hr][tx] = __float2half(Wd[(size_t)(h0 + hr) * VV + v0 + tx]);
    }
    __syncthreads();
#pragma unroll
    for (int j = 0; j < 4; j++) {
        int vr = ty + j * 8;
        g_b_h[(size_t)(v0 + vr) * HH + h0 + tx] = sh[tx][vr];
    }
}

// ------------------------- HMMA dense GEMM (fp16, single pass) ------------------
// C[4096, 32000] = h2 @ Wd^T + bd. CTA tile 128x128, warp tile 64x32.
// K=512 in 16 chunks of 32, double-buffered via cp.async.
// smem per stage: A | B, each 128 rows x 32 fp16, row stride 40 halfs (80 B).
#define DARR 10240u          // bytes per sub-array (128*80)
#define DSTG 20480u          // bytes per stage (2 arrays)

__device__ __forceinline__ void dense_load_chunk(uint32_t sb, int m0, int n0, int c, int tid)
{
    const uint32_t stg = sb + (uint32_t)(c & 1) * DSTG;
    const int kc0 = c * 32;
#pragma unroll
    for (int it = 0; it < 4; it++) {
        int u = tid + it * 256;          // 0..1023 16B units
        int arr = u >> 9;                // 0 A, 1 B
        int u2 = u & 511;
        int r = u2 >> 2, q = u2 & 3;
        const __half* g = arr ? g_b_h : g_a_h;
        int grow = arr ? n0 : m0;
        cp_async16(stg + (uint32_t)arr * DARR + (uint32_t)(r * 80 + q * 16),
                   g + (size_t)(grow + r) * HH + kc0 + q * 8);
    }
    cp_commit();
}

__global__ __launch_bounds__(256, 2)
void dense_kernel(const float* __restrict__ bd, float* __restrict__ out)
{
    extern __shared__ char smem[];
    const uint32_t sb = smem_u32(smem);
    const int tid = threadIdx.x;
    const int wid = tid >> 5;
    const int lane = tid & 31;
    const int n0 = blockIdx.x * 128;
    const int m0 = blockIdx.y * 128;
    const int wm = wid & 1;              // 2 warps along M (64 rows each)
    const int wn = wid >> 1;             // 4 warps along N (32 cols each)
    const int lrow = lane & 15;
    const int lsel = (lane >> 4) << 4;   // 0 or 16 bytes (k half)

    float acc[4][4][4];                  // [mt][nt][4]
#pragma unroll
    for (int mt = 0; mt < 4; mt++)
#pragma unroll
        for (int nt = 0; nt < 4; nt++)
#pragma unroll
            for (int e = 0; e < 4; e++) acc[mt][nt][e] = 0.f;

    dense_load_chunk(sb, m0, n0, 0, tid);

    for (int c = 0; c < 16; c++) {
        if (c < 15) {
            dense_load_chunk(sb, m0, n0, c + 1, tid);
            cp_wait<1>();
        } else {
            cp_wait<0>();
        }
        __syncthreads();
        const uint32_t stg = sb + (uint32_t)(c & 1) * DSTG;
        const uint32_t a_b = stg + (uint32_t)((wm * 64 + lrow) * 80) + lsel;
        const uint32_t b_b = stg + DARR + (uint32_t)((wn * 32 + lrow) * 80) + lsel;
#pragma unroll
        for (int s = 0; s < 2; s++) {
            uint32_t bf[2][4];
#pragma unroll
            for (int i = 0; i < 2; i++)
                ldm_x4(bf[i], b_b + (uint32_t)(i * 16 * 80 + s * 32));
#pragma unroll
            for (int mt = 0; mt < 4; mt++) {
                uint32_t a[4];
                ldm_x4(a, a_b + (uint32_t)(mt * 16 * 80 + s * 32));
#pragma unroll
                for (int nt = 0; nt < 4; nt++) {
                    uint32_t b0 = bf[nt >> 1][nt & 1];
                    uint32_t b1 = bf[nt >> 1][(nt & 1) + 2];
                    mma_f16(acc[mt][nt], a, b0, b1);
                }
            }
        }
        __syncthreads();
    }

    // epilogue: direct stores with [t*16+b] -> [b*256+t] row remap
    const int g = lane >> 2;
    const int tig = lane & 3;
#pragma unroll
    for (int nt = 0; nt < 4; nt++) {
        int col = n0 + wn * 32 + nt * 8 + tig * 2;
        float b0 = __ldg(bd + col);
        float b1 = __ldg(bd + col + 1);
#pragma unroll
        for (int mt = 0; mt < 4; mt++) {
            int r0 = m0 + wm * 64 + mt * 16 + g;
            int r1 = r0 + 8;
            size_t o0 = (size_t)((r0 & 15) * 256 + (r0 >> 4));
            size_t o1 = (size_t)((r1 & 15) * 256 + (r1 >> 4));
            float2 v0 = make_float2(acc[mt][nt][0] + b0, acc[mt][nt][1] + b1);
            float2 v1 = make_float2(acc[mt][nt][2] + b0, acc[mt][nt][3] + b1);
            *(float2*)(out + o0 * VV + col) = v0;
            *(float2*)(out + o1 * VV + col) = v1;
        }
    }
}

// ------------------------- launch -----------------------------------------------
extern "C" void kernel_launch(void* const* d_in, const int* in_sizes, int n_in,
                              void* d_out, int out_size)
{
    const int*   tokens = (const int*)  d_in[0];
    const float* emb    = (const float*)d_in[1];
    const float* W1     = (const float*)d_in[2];
    const float* U1     = (const float*)d_in[3];
    const float* b1     = (const float*)d_in[4];
    const float* W2     = (const float*)d_in[5];
    const float* U2     = (const float*)d_in[6];
    const float* b2     = (const float*)d_in[7];
    const float* Wd     = (const float*)d_in[8];
    const float* bd     = (const float*)d_in[9];
    float* out = (float*)d_out;

    cudaFuncSetAttribute(dense_kernel, cudaFuncAttributeMaxDynamicSharedMemorySize,
                         (int)(2 * DSTG));

    // B transpose/convert is independent of everything else — do it first
    transB_kernel<<<dim3(VV / 32, HH / 32), dim3(32, 8)>>>(Wd);
    // 1) xw1 = gather(emb, tokens) @ W1 + b1     rows r = t*16+b
    sgemm_kernel<0, MROWS, G4H, EE><<<dim3(G4H / 128, MROWS / 128), 256>>>(
        emb, W1, b1, nullptr, tokens);
    // 2) LSTM layer 1 -> g_h1
    lstm_kernel<<<NCTA_LSTM, 256>>>(U1, 0);
    // 3) xw2 = g_h1 @ W2 + b2
    sgemm_kernel<1, MROWS, G4H, HH><<<dim3(G4H / 128, MROWS / 128), 256>>>(
        nullptr, W2, b2, nullptr, nullptr);
    // 4) LSTM layer 2 -> g_h2
    lstm_kernel<<<NCTA_LSTM, 256>>>(U2, 1);
    // 5) convert h2 to fp16
    convA_kernel<<<(MROWS * HH) / (256 * 4), 256>>>();
    // 6) logits = h2 @ Wd + bd on HMMA tensor cores (fp16 single pass)
    dense_kernel<<<dim3(VV / 128, MROWS / 128), 256, 2 * DSTG>>>(bd, out);
}

// round 5
// speedup vs baseline: 3.2747x; 1.4571x over previous
#include <cuda_runtime.h>
#include <cuda_bf16.h>
#include <cuda_fp16.h>
#include <math.h>
#include <stdint.h>

// Problem constants
#define BB 16
#define TT 256
#define EE 256
#define HH 512
#define G4H 2048
#define VV 32000
#define MROWS 4096           // B*T, row r = t*16 + b
#define NCTA_LSTM 128

// ------------------------- scratch (no mallocs allowed) -------------------------
__device__ float g_xw[(size_t)MROWS * G4H];     // xw1 = emb@W1+b1
__device__ float g_h1b[2][BB * HH];             // h1 ping-pong
__device__ float g_h2b[2][BB * HH];             // h2 ping-pong
__device__ unsigned g_bar_count;
__device__ unsigned g_bar_gen;

// fp16 operands for the tensor-core dense layer
__device__ __half g_a_h[(size_t)MROWS * HH];    // 4 MB  (written by LSTM writers)
__device__ __half g_b_h[(size_t)VV * HH];       // 32.8 MB, [v][h] transposed Wd

// ------------------------- small PTX helpers ------------------------------------
__device__ __forceinline__ uint32_t smem_u32(const void* p) {
    uint32_t a;
    asm("{ .reg .u64 t; cvta.to.shared.u64 t, %1; cvt.u32.u64 %0, t; }" : "=r"(a) : "l"(p));
    return a;
}
__device__ __forceinline__ void cp_async16(uint32_t saddr, const void* gptr) {
    asm volatile("cp.async.cg.shared.global [%0], [%1], 16;"
                 :: "r"(saddr), "l"(__cvta_generic_to_global(gptr)) : "memory");
}
__device__ __forceinline__ void cp_commit() {
    asm volatile("cp.async.commit_group;" ::: "memory");
}
template<int N>
__device__ __forceinline__ void cp_wait() {
    asm volatile("cp.async.wait_group %0;" :: "n"(N) : "memory");
}
__device__ __forceinline__ void ldm_x4(uint32_t* r, uint32_t a) {
    asm volatile("ldmatrix.sync.aligned.m8n8.x4.shared.b16 {%0,%1,%2,%3}, [%4];"
                 : "=r"(r[0]), "=r"(r[1]), "=r"(r[2]), "=r"(r[3]) : "r"(a));
}
__device__ __forceinline__ void mma_f16(float* d, const uint32_t* a, uint32_t b0, uint32_t b1) {
    asm volatile(
        "mma.sync.aligned.m16n8k16.row.col.f32.f16.f16.f32 "
        "{%0,%1,%2,%3}, {%4,%5,%6,%7}, {%8,%9}, {%0,%1,%2,%3};"
        : "+f"(d[0]), "+f"(d[1]), "+f"(d[2]), "+f"(d[3])
        : "r"(a[0]), "r"(a[1]), "r"(a[2]), "r"(a[3]), "r"(b0), "r"(b1));
}
// packed fp32x2 (Blackwell): 2 MACs per instruction
typedef unsigned long long ull;
__device__ __forceinline__ ull pk2(float lo, float hi) {
    ull r;
    asm("mov.b64 %0, {%1, %2};" : "=l"(r) : "f"(lo), "f"(hi));
    return r;
}
__device__ __forceinline__ ull fma2(ull a, ull b, ull c) {
    ull d;
    asm("fma.rn.f32x2 %0, %1, %2, %3;" : "=l"(d) : "l"(a), "l"(b), "l"(c));
    return d;
}
__device__ __forceinline__ float sum2(ull a) {
    float lo, hi;
    asm("mov.b64 {%0, %1}, %2;" : "=f"(lo), "=f"(hi) : "l"(a));
    return lo + hi;
}
__device__ __forceinline__ void lds_v2u64(ull& a, ull& b, uint32_t addr) {
    asm volatile("ld.shared.v2.u64 {%0, %1}, [%2];" : "=l"(a), "=l"(b) : "r"(addr));
}

// ------------------------- global barrier (all CTAs resident) -------------------
__device__ __forceinline__ void grid_barrier(int ncta) {
    __syncthreads();
    if (threadIdx.x == 0) {
        __threadfence();
        unsigned gen = *(volatile unsigned*)&g_bar_gen;
        if (atomicAdd(&g_bar_count, 1u) == (unsigned)(ncta - 1)) {
            g_bar_count = 0;
            __threadfence();
            *(volatile unsigned*)&g_bar_gen = gen + 1u;
        } else {
            while (*(volatile unsigned*)&g_bar_gen == gen) { }
            __threadfence();
        }
    }
    __syncthreads();
}

// ------------------------- SGEMM 128x128 tile (fp32): xw1 only ------------------
__global__ __launch_bounds__(256, 2)
void sgemm0_kernel(const float* __restrict__ emb,
                   const float* __restrict__ W1,
                   const float* __restrict__ b1,
                   const int* __restrict__ tokens)
{
    const int K = EE, N = G4H;
    __shared__ float As[16][128];
    __shared__ float Bs[16][128];

    const int tid = threadIdx.x;
    const int m0 = blockIdx.y * 128;
    const int n0 = blockIdx.x * 128;
    const int rg = (tid >> 4) * 4;
    const int cg = (tid & 15) * 4;

    float acc[8][8];
#pragma unroll
    for (int i = 0; i < 8; i++)
#pragma unroll
        for (int j = 0; j < 8; j++) acc[i][j] = 0.f;

    for (int kt = 0; kt < K; kt += 16) {
        __syncthreads();
#pragma unroll
        for (int it = 0; it < 2; it++) {
            int item = tid + it * 256;
            int m = item >> 2;
            int kq = item & 3;
            int gr = m0 + m;
            int tok = tokens[((gr & 15) << 8) + (gr >> 4)];
            float4 v = *(const float4*)(emb + (size_t)tok * K + kt + kq * 4);
            As[kq * 4 + 0][m] = v.x;
            As[kq * 4 + 1][m] = v.y;
            As[kq * 4 + 2][m] = v.z;
            As[kq * 4 + 3][m] = v.w;
        }
#pragma unroll
        for (int it = 0; it < 2; it++) {
            int item = tid + it * 256;
            int k = item >> 5;
            int n4 = item & 31;
            float4 v = *(const float4*)(W1 + (size_t)(kt + k) * N + n0 + n4 * 4);
            *(float4*)&Bs[k][n4 * 4] = v;
        }
        __syncthreads();
#pragma unroll
        for (int kk = 0; kk < 16; kk++) {
            float4 a0 = *(const float4*)&As[kk][rg];
            float4 a1 = *(const float4*)&As[kk][64 + rg];
            float4 b0 = *(const float4*)&Bs[kk][cg];
            float4 b1 = *(const float4*)&Bs[kk][64 + cg];
            float a[8] = {a0.x, a0.y, a0.z, a0.w, a1.x, a1.y, a1.z, a1.w};
            float b[8] = {b0.x, b0.y, b0.z, b0.w, b1.x, b1.y, b1.z, b1.w};
#pragma unroll
            for (int i = 0; i < 8; i++)
#pragma unroll
                for (int j = 0; j < 8; j++)
                    acc[i][j] += a[i] * b[j];
        }
    }

    float bj[8];
#pragma unroll
    for (int j = 0; j < 4; j++) {
        bj[j]     = b1[n0 + cg + j];
        bj[4 + j] = b1[n0 + 64 + cg + j];
    }
#pragma unroll
    for (int i = 0; i < 8; i++) {
        int r = m0 + ((i < 4) ? (rg + i) : (64 + rg + i - 4));
        float4 o0, o1;
        o0.x = acc[i][0] + bj[0]; o0.y = acc[i][1] + bj[1];
        o0.z = acc[i][2] + bj[2]; o0.w = acc[i][3] + bj[3];
        o1.x = acc[i][4] + bj[4]; o1.y = acc[i][5] + bj[5];
        o1.z = acc[i][6] + bj[6]; o1.w = acc[i][7] + bj[7];
        *(float4*)&g_xw[(size_t)r * N + n0 + cg]      = o0;
        *(float4*)&g_xw[(size_t)r * N + n0 + 64 + cg] = o1;
    }
}

// ------------------------- fused dual-layer pipelined LSTM ----------------------
// 128 CTAs x 256 threads, persistent. CTA ct owns hidden units hu0..hu0+3 for
// BOTH layers. At global step s: compute h1[s] (s<256) and h2[s-1] (s>=1).
// z1[s] = xw1[s] + h1[s-1]@U1 ; z2[s-1] = b2 + h1[s-1]@W2 + h2[s-2]@U2.
// Thread (ks=tid/16, lc=tid%16) holds 3x32 weight values packed as f32x2 regs.
// Smem layout (floats):
//   0      h1s[8192]          h1[s-1] staging
//   8192   h2s[8192]          h2[s-2] staging
//   16384  p1[16*16*17]       z1 partials [b][ks][lc], pad 17
//   20736  p2[16*16*17]       z2 partials
//   25088  zsh1[256]  25344 zsh2[256]  25600 c1[64]  25664 c2[64]
#define LSM_FLOATS 25728
__global__ __launch_bounds__(256, 1)
void lstm_fused_kernel(const float* __restrict__ U1,
                       const float* __restrict__ W2,
                       const float* __restrict__ U2,
                       const float* __restrict__ b2)
{
    extern __shared__ float ls[];
    float* h1s = ls;
    float* h2s = ls + 8192;
    float* p1  = ls + 16384;
    float* p2  = ls + 20736;
    float* zsh1 = ls + 25088;
    float* zsh2 = ls + 25344;
    float* c1s  = ls + 25600;
    float* c2s  = ls + 25664;

    const int tid = threadIdx.x;
    const int ct = blockIdx.x;
    const int hu0 = ct * 4;
    const int ks = tid >> 4;
    const int lc = tid & 15;
    const int gc = ((lc >> 2) << 9) + hu0 + (lc & 3);
    const uint32_t h1s_a = smem_u32(h1s);
    const uint32_t h2s_a = smem_u32(h2s);

    // one-time: pack 3x32 weights into f32x2 registers
    ull u1p[16], w2p[16], u2p[16];
#pragma unroll
    for (int j = 0; j < 16; j++) {
        int k0 = ks * 32 + 2 * j;
        u1p[j] = pk2(U1[(size_t)k0 * G4H + gc], U1[(size_t)(k0 + 1) * G4H + gc]);
        w2p[j] = pk2(W2[(size_t)k0 * G4H + gc], W2[(size_t)(k0 + 1) * G4H + gc]);
        u2p[j] = pk2(U2[(size_t)k0 * G4H + gc], U2[(size_t)(k0 + 1) * G4H + gc]);
    }
    const float b2v = __ldg(b2 + gc);

    // zero staging buffers + cell states
#pragma unroll
    for (int i = 0; i < 16; i++)
        *(float4*)(h1s + (tid + i * 256) * 4) = make_float4(0.f, 0.f, 0.f, 0.f);
    if (tid < 64) { c1s[tid] = 0.f; c2s[tid] = 0.f; }
    __syncthreads();

    for (int s = 0; s <= TT; s++) {
        float xwv = (s < TT) ? __ldg(&g_xw[((size_t)s * BB + ks) * G4H + gc]) : 0.f;

        // stage h1[s-1], h2[s-2]
        if (s >= 1) {
            const float* hp = g_h1b[(s - 1) & 1];
#pragma unroll
            for (int i = 0; i < 8; i++) {
                int idx = tid + i * 256;
                cp_async16(h1s_a + (uint32_t)idx * 16u, hp + idx * 4);
            }
            if (s >= 2) {
                const float* hq = g_h2b[s & 1];
#pragma unroll
                for (int i = 0; i < 8; i++) {
                    int idx = tid + i * 256;
                    cp_async16(h2s_a + (uint32_t)idx * 16u, hq + idx * 4);
                }
            }
            cp_commit();
            cp_wait<0>();
            __syncthreads();
        }

        // partial dots: 16 b x 32 k, packed f32x2
#pragma unroll 2
        for (int b = 0; b < 16; b++) {
            uint32_t a1addr = h1s_a + (uint32_t)((b * 512 + ks * 32) * 4);
            uint32_t a2addr = h2s_a + (uint32_t)((b * 512 + ks * 32) * 4);
            ull acc1 = 0, accw = 0, acc2 = 0;
#pragma unroll
            for (int i = 0; i < 8; i++) {
                ull q0, q1;
                lds_v2u64(q0, q1, a1addr + (uint32_t)(i * 16));
                acc1 = fma2(q0, u1p[2 * i], acc1);
                acc1 = fma2(q1, u1p[2 * i + 1], acc1);
                accw = fma2(q0, w2p[2 * i], accw);
                accw = fma2(q1, w2p[2 * i + 1], accw);
                ull r0, r1;
                lds_v2u64(r0, r1, a2addr + (uint32_t)(i * 16));
                acc2 = fma2(r0, u2p[2 * i], acc2);
                acc2 = fma2(r1, u2p[2 * i + 1], acc2);
            }
            p1[b * 272 + ks * 17 + lc] = sum2(acc1);
            p2[b * 272 + ks * 17 + lc] = sum2(accw) + sum2(acc2);
        }
        __syncthreads();

        // reduce over 16 k-slices for (b=ks, lc)
        float z1 = xwv, z2 = b2v;
#pragma unroll
        for (int k = 0; k < 16; k++) {
            z1 += p1[ks * 272 + k * 17 + lc];
            z2 += p2[ks * 272 + k * 17 + lc];
        }
        zsh1[ks * 16 + lc] = z1;
        zsh2[ks * 16 + lc] = z2;
        __syncthreads();

        if (tid < 64) {
            int bb = tid >> 2, j = tid & 3;
            if (s < TT) {
                float zi = zsh1[bb * 16 + j];
                float zf = zsh1[bb * 16 + 4 + j];
                float zg = zsh1[bb * 16 + 8 + j];
                float zo = zsh1[bb * 16 + 12 + j];
                float ig = 1.f / (1.f + expf(-zi));
                float fg = 1.f / (1.f + expf(-zf));
                float gg = tanhf(zg);
                float og = 1.f / (1.f + expf(-zo));
                float c = fg * c1s[bb * 4 + j] + ig * gg;
                c1s[bb * 4 + j] = c;
                g_h1b[s & 1][bb * HH + hu0 + j] = og * tanhf(c);
            }
            if (s >= 1) {
                int t = s - 1;
                float zi = zsh2[bb * 16 + j];
                float zf = zsh2[bb * 16 + 4 + j];
                float zg = zsh2[bb * 16 + 8 + j];
                float zo = zsh2[bb * 16 + 12 + j];
                float ig = 1.f / (1.f + expf(-zi));
                float fg = 1.f / (1.f + expf(-zf));
                float gg = tanhf(zg);
                float og = 1.f / (1.f + expf(-zo));
                float c = fg * c2s[bb * 4 + j] + ig * gg;
                c2s[bb * 4 + j] = c;
                float h = og * tanhf(c);
                g_h2b[t & 1][bb * HH + hu0 + j] = h;
                g_a_h[((size_t)t * BB + bb) * HH + hu0 + j] = __float2half(h);
            }
            __threadfence();
        }
        grid_barrier(NCTA_LSTM);
    }
}

// ------------------------- fp16 B transpose -------------------------------------
// Wd [512][32000] fp32 -> g_b_h [32000][512] fp16 (tiled transpose)
__global__ void transB_kernel(const float* __restrict__ Wd)
{
    __shared__ __half sh[32][33];
    const int v0 = blockIdx.x * 32;
    const int h0 = blockIdx.y * 32;
    const int tx = threadIdx.x;
    const int ty = threadIdx.y;
#pragma unroll
    for (int j = 0; j < 4; j++) {
        int hr = ty + j * 8;
        sh[hr][tx] = __float2half(Wd[(size_t)(h0 + hr) * VV + v0 + tx]);
    }
    __syncthreads();
#pragma unroll
    for (int j = 0; j < 4; j++) {
        int vr = ty + j * 8;
        g_b_h[(size_t)(v0 + vr) * HH + h0 + tx] = sh[tx][vr];
    }
}

// ------------------------- HMMA dense GEMM (fp16, 3-stage pipeline) -------------
// C[4096, 32000] = h2 @ Wd^T + bd. CTA tile 128x128, warp tile 64x32.
// K=512 in 16 chunks of 32, triple-buffered via cp.async, 1 sync per chunk.
#define DARR 10240u          // bytes per sub-array (128*80)
#define DSTG 20480u          // bytes per stage (A|B)

__device__ __forceinline__ void dense_load_chunk(uint32_t sb, int m0, int n0, int c, int tid)
{
    const uint32_t stg = sb + (uint32_t)(c % 3) * DSTG;
    const int kc0 = c * 32;
#pragma unroll
    for (int it = 0; it < 4; it++) {
        int u = tid + it * 256;          // 0..1023 16B units
        int arr = u >> 9;                // 0 A, 1 B
        int u2 = u & 511;
        int r = u2 >> 2, q = u2 & 3;
        const __half* g = arr ? g_b_h : g_a_h;
        int grow = arr ? n0 : m0;
        cp_async16(stg + (uint32_t)arr * DARR + (uint32_t)(r * 80 + q * 16),
                   g + (size_t)(grow + r) * HH + kc0 + q * 8);
    }
    cp_commit();
}

__global__ __launch_bounds__(256, 2)
void dense_kernel(const float* __restrict__ bd, float* __restrict__ out)
{
    extern __shared__ char smem[];
    const uint32_t sb = smem_u32(smem);
    const int tid = threadIdx.x;
    const int wid = tid >> 5;
    const int lane = tid & 31;
    const int n0 = blockIdx.x * 128;
    const int m0 = blockIdx.y * 128;
    const int wm = wid & 1;
    const int wn = wid >> 1;
    const int lrow = lane & 15;
    const int lsel = (lane >> 4) << 4;

    float acc[4][4][4];
#pragma unroll
    for (int mt = 0; mt < 4; mt++)
#pragma unroll
        for (int nt = 0; nt < 4; nt++)
#pragma unroll
            for (int e = 0; e < 4; e++) acc[mt][nt][e] = 0.f;

    dense_load_chunk(sb, m0, n0, 0, tid);
    dense_load_chunk(sb, m0, n0, 1, tid);

    for (int c = 0; c < 16; c++) {
        if (c < 15) cp_wait<1>(); else cp_wait<0>();
        __syncthreads();
        if (c + 2 < 16) dense_load_chunk(sb, m0, n0, c + 2, tid);

        const uint32_t stg = sb + (uint32_t)(c % 3) * DSTG;
        const uint32_t a_b = stg + (uint32_t)((wm * 64 + lrow) * 80) + lsel;
        const uint32_t b_b = stg + DARR + (uint32_t)((wn * 32 + lrow) * 80) + lsel;
#pragma unroll
        for (int s = 0; s < 2; s++) {
            uint32_t bf[2][4];
#pragma unroll
            for (int i = 0; i < 2; i++)
                ldm_x4(bf[i], b_b + (uint32_t)(i * 16 * 80 + s * 32));
#pragma unroll
            for (int mt = 0; mt < 4; mt++) {
                uint32_t a[4];
                ldm_x4(a, a_b + (uint32_t)(mt * 16 * 80 + s * 32));
#pragma unroll
                for (int nt = 0; nt < 4; nt++) {
                    uint32_t b0 = bf[nt >> 1][nt & 1];
                    uint32_t b1 = bf[nt >> 1][(nt & 1) + 2];
                    mma_f16(acc[mt][nt], a, b0, b1);
                }
            }
        }
    }

    // epilogue: direct stores with [t*16+b] -> [b*256+t] row remap
    const int g = lane >> 2;
    const int tig = lane & 3;
#pragma unroll
    for (int nt = 0; nt < 4; nt++) {
        int col = n0 + wn * 32 + nt * 8 + tig * 2;
        float b0 = __ldg(bd + col);
        float b1 = __ldg(bd + col + 1);
#pragma unroll
        for (int mt = 0; mt < 4; mt++) {
            int r0 = m0 + wm * 64 + mt * 16 + g;
            int r1 = r0 + 8;
            size_t o0 = (size_t)((r0 & 15) * 256 + (r0 >> 4));
            size_t o1 = (size_t)((r1 & 15) * 256 + (r1 >> 4));
            float2 v0 = make_float2(acc[mt][nt][0] + b0, acc[mt][nt][1] + b1);
            float2 v1 = make_float2(acc[mt][nt][2] + b0, acc[mt][nt][3] + b1);
            *(float2*)(out + o0 * VV + col) = v0;
            *(float2*)(out + o1 * VV + col) = v1;
        }
    }
}

// ------------------------- launch -----------------------------------------------
extern "C" void kernel_launch(void* const* d_in, const int* in_sizes, int n_in,
                              void* d_out, int out_size)
{
    const int*   tokens = (const int*)  d_in[0];
    const float* emb    = (const float*)d_in[1];
    const float* W1     = (const float*)d_in[2];
    const float* U1     = (const float*)d_in[3];
    const float* b1     = (const float*)d_in[4];
    const float* W2     = (const float*)d_in[5];
    const float* U2     = (const float*)d_in[6];
    const float* b2     = (const float*)d_in[7];
    const float* Wd     = (const float*)d_in[8];
    const float* bd     = (const float*)d_in[9];
    float* out = (float*)d_out;

    cudaFuncSetAttribute(dense_kernel, cudaFuncAttributeMaxDynamicSharedMemorySize,
                         (int)(3 * DSTG));
    cudaFuncSetAttribute(lstm_fused_kernel, cudaFuncAttributeMaxDynamicSharedMemorySize,
                         (int)(LSM_FLOATS * sizeof(float)));

    // B transpose/convert is independent of everything else — do it first
    transB_kernel<<<dim3(VV / 32, HH / 32), dim3(32, 8)>>>(Wd);
    // 1) xw1 = gather(emb, tokens) @ W1 + b1     rows r = t*16+b
    sgemm0_kernel<<<dim3(G4H / 128, MROWS / 128), 256>>>(emb, W1, b1, tokens);
    // 2) fused dual-layer LSTM (z2 includes h1@W2+b2); writes fp16 g_a_h directly
    lstm_fused_kernel<<<NCTA_LSTM, 256, LSM_FLOATS * sizeof(float)>>>(U1, W2, U2, b2);
    // 3) logits = h2 @ Wd + bd on HMMA tensor cores (fp16 single pass)
    dense_kernel<<<dim3(VV / 128, MROWS / 128), 256, 3 * DSTG>>>(bd, out);
}

// round 6
// speedup vs baseline: 3.4266x; 1.0464x over previous
#include <cuda_runtime.h>
#include <cuda_bf16.h>
#include <cuda_fp16.h>
#include <math.h>
#include <stdint.h>

// Problem constants
#define BB 16
#define TT 256
#define EE 256
#define HH 512
#define G4H 2048
#define VV 32000
#define MROWS 4096           // B*T, row r = t*16 + b
#define NCTA_LSTM 128

// ------------------------- scratch (no mallocs allowed) -------------------------
__device__ float g_xw[(size_t)MROWS * G4H];     // xw1 = emb@W1+b1
__device__ float g_h1b[2][BB * HH];             // h1 ping-pong
__device__ float g_h2b[2][BB * HH];             // h2 ping-pong
__device__ unsigned g_bar_count;
__device__ unsigned g_bar_gen;

// fp16 operands for the tensor-core dense layer
__device__ __half g_a_h[(size_t)MROWS * HH];    // 4 MB  (written by LSTM writers)
__device__ __half g_b_h[(size_t)VV * HH];       // 32.8 MB, [v][h] transposed Wd

// ------------------------- small PTX helpers ------------------------------------
__device__ __forceinline__ uint32_t smem_u32(const void* p) {
    uint32_t a;
    asm("{ .reg .u64 t; cvta.to.shared.u64 t, %1; cvt.u32.u64 %0, t; }" : "=r"(a) : "l"(p));
    return a;
}
__device__ __forceinline__ void cp_async16(uint32_t saddr, const void* gptr) {
    asm volatile("cp.async.cg.shared.global [%0], [%1], 16;"
                 :: "r"(saddr), "l"(__cvta_generic_to_global(gptr)) : "memory");
}
__device__ __forceinline__ void cp_commit() {
    asm volatile("cp.async.commit_group;" ::: "memory");
}
template<int N>
__device__ __forceinline__ void cp_wait() {
    asm volatile("cp.async.wait_group %0;" :: "n"(N) : "memory");
}
__device__ __forceinline__ void ldm_x4(uint32_t* r, uint32_t a) {
    asm volatile("ldmatrix.sync.aligned.m8n8.x4.shared.b16 {%0,%1,%2,%3}, [%4];"
                 : "=r"(r[0]), "=r"(r[1]), "=r"(r[2]), "=r"(r[3]) : "r"(a));
}
__device__ __forceinline__ void mma_f16(float* d, const uint32_t* a, uint32_t b0, uint32_t b1) {
    asm volatile(
        "mma.sync.aligned.m16n8k16.row.col.f32.f16.f16.f32 "
        "{%0,%1,%2,%3}, {%4,%5,%6,%7}, {%8,%9}, {%0,%1,%2,%3};"
        : "+f"(d[0]), "+f"(d[1]), "+f"(d[2]), "+f"(d[3])
        : "r"(a[0]), "r"(a[1]), "r"(a[2]), "r"(a[3]), "r"(b0), "r"(b1));
}
// packed fp32x2 (Blackwell): 2 MACs per instruction
typedef unsigned long long ull;
__device__ __forceinline__ ull pk2(float lo, float hi) {
    ull r;
    asm("mov.b64 %0, {%1, %2};" : "=l"(r) : "f"(lo), "f"(hi));
    return r;
}
__device__ __forceinline__ ull fma2(ull a, ull b, ull c) {
    ull d;
    asm("fma.rn.f32x2 %0, %1, %2, %3;" : "=l"(d) : "l"(a), "l"(b), "l"(c));
    return d;
}
__device__ __forceinline__ float sum2(ull a) {
    float lo, hi;
    asm("mov.b64 {%0, %1}, %2;" : "=f"(lo), "=f"(hi) : "l"(a));
    return lo + hi;
}
__device__ __forceinline__ void lds_v2u64(ull& a, ull& b, uint32_t addr) {
    asm volatile("ld.shared.v2.u64 {%0, %1}, [%2];" : "=l"(a), "=l"(b) : "r"(addr));
}

// ------------------------- global barrier (all CTAs resident) -------------------
__device__ __forceinline__ void grid_barrier(int ncta) {
    __syncthreads();
    if (threadIdx.x == 0) {
        __threadfence();
        unsigned gen = *(volatile unsigned*)&g_bar_gen;
        if (atomicAdd(&g_bar_count, 1u) == (unsigned)(ncta - 1)) {
            g_bar_count = 0;
            __threadfence();
            *(volatile unsigned*)&g_bar_gen = gen + 1u;
        } else {
            while (*(volatile unsigned*)&g_bar_gen == gen) { }
            __threadfence();
        }
    }
    __syncthreads();
}

// ------------------------- SGEMM 128x128 tile (fp32): xw1 only ------------------
__global__ __launch_bounds__(256, 2)
void sgemm0_kernel(const float* __restrict__ emb,
                   const float* __restrict__ W1,
                   const float* __restrict__ b1,
                   const int* __restrict__ tokens)
{
    const int K = EE, N = G4H;
    __shared__ float As[16][128];
    __shared__ float Bs[16][128];

    const int tid = threadIdx.x;
    const int m0 = blockIdx.y * 128;
    const int n0 = blockIdx.x * 128;
    const int rg = (tid >> 4) * 4;
    const int cg = (tid & 15) * 4;

    float acc[8][8];
#pragma unroll
    for (int i = 0; i < 8; i++)
#pragma unroll
        for (int j = 0; j < 8; j++) acc[i][j] = 0.f;

    for (int kt = 0; kt < K; kt += 16) {
        __syncthreads();
#pragma unroll
        for (int it = 0; it < 2; it++) {
            int item = tid + it * 256;
            int m = item >> 2;
            int kq = item & 3;
            int gr = m0 + m;
            int tok = tokens[((gr & 15) << 8) + (gr >> 4)];
            float4 v = *(const float4*)(emb + (size_t)tok * K + kt + kq * 4);
            As[kq * 4 + 0][m] = v.x;
            As[kq * 4 + 1][m] = v.y;
            As[kq * 4 + 2][m] = v.z;
            As[kq * 4 + 3][m] = v.w;
        }
#pragma unroll
        for (int it = 0; it < 2; it++) {
            int item = tid + it * 256;
            int k = item >> 5;
            int n4 = item & 31;
            float4 v = *(const float4*)(W1 + (size_t)(kt + k) * N + n0 + n4 * 4);
            *(float4*)&Bs[k][n4 * 4] = v;
        }
        __syncthreads();
#pragma unroll
        for (int kk = 0; kk < 16; kk++) {
            float4 a0 = *(const float4*)&As[kk][rg];
            float4 a1 = *(const float4*)&As[kk][64 + rg];
            float4 b0 = *(const float4*)&Bs[kk][cg];
            float4 b1 = *(const float4*)&Bs[kk][64 + cg];
            float a[8] = {a0.x, a0.y, a0.z, a0.w, a1.x, a1.y, a1.z, a1.w};
            float b[8] = {b0.x, b0.y, b0.z, b0.w, b1.x, b1.y, b1.z, b1.w};
#pragma unroll
            for (int i = 0; i < 8; i++)
#pragma unroll
                for (int j = 0; j < 8; j++)
                    acc[i][j] += a[i] * b[j];
        }
    }

    float bj[8];
#pragma unroll
    for (int j = 0; j < 4; j++) {
        bj[j]     = b1[n0 + cg + j];
        bj[4 + j] = b1[n0 + 64 + cg + j];
    }
#pragma unroll
    for (int i = 0; i < 8; i++) {
        int r = m0 + ((i < 4) ? (rg + i) : (64 + rg + i - 4));
        float4 o0, o1;
        o0.x = acc[i][0] + bj[0]; o0.y = acc[i][1] + bj[1];
        o0.z = acc[i][2] + bj[2]; o0.w = acc[i][3] + bj[3];
        o1.x = acc[i][4] + bj[4]; o1.y = acc[i][5] + bj[5];
        o1.z = acc[i][6] + bj[6]; o1.w = acc[i][7] + bj[7];
        *(float4*)&g_xw[(size_t)r * N + n0 + cg]      = o0;
        *(float4*)&g_xw[(size_t)r * N + n0 + 64 + cg] = o1;
    }
}

// ------------------------- fused dual-layer pipelined LSTM (512 thr) ------------
// 128 CTAs x 512 threads, persistent. CTA ct owns hidden units hu0..hu0+3 for
// BOTH layers. At step s: compute h1[s] (s<256) and h2[s-1] (s>=1).
// z1 = xw1 + h1[s-1]@U1 ; z2 = b2 + h1[s-1]@W2 + h2[s-2]@U2.
// Thread (ks=tid/16 in 0..31, lc=tid%16): 16 k-values per matrix in f32x2 regs.
// h staging double-chunked via cp.async (b 0-7 | b 8-15) to overlap L2 reads.
// Smem floats: h1s 8192 | h2s 8192 | p1 8704 | p2 8704 | zsh1 256 | zsh2 256
//              c1 64 | c2 64   (p stride: b*544 + lc*34 + ks, bank-conflict-free)
#define LSM_FLOATS 34432
__global__ __launch_bounds__(512, 1)
void lstm_fused_kernel(const float* __restrict__ U1,
                       const float* __restrict__ W2,
                       const float* __restrict__ U2,
                       const float* __restrict__ b2)
{
    extern __shared__ float ls[];
    float* h1s  = ls;
    float* h2s  = ls + 8192;
    float* p1   = ls + 16384;
    float* p2   = ls + 25088;
    float* zsh1 = ls + 33792;
    float* zsh2 = ls + 34048;
    float* c1s  = ls + 34304;
    float* c2s  = ls + 34368;

    const int tid = threadIdx.x;
    const int ct = blockIdx.x;
    const int hu0 = ct * 4;
    const int ks = tid >> 4;            // 0..31
    const int lc = tid & 15;
    const int gc = ((lc >> 2) << 9) + hu0 + (lc & 3);
    const uint32_t h1s_a = smem_u32(h1s);
    const uint32_t h2s_a = smem_u32(h2s);
    const int k0 = ks * 16;

    // one-time: pack 3x16 weights into f32x2 registers
    ull u1p[8], w2p[8], u2p[8];
#pragma unroll
    for (int j = 0; j < 8; j++) {
        int kk = k0 + 2 * j;
        u1p[j] = pk2(U1[(size_t)kk * G4H + gc], U1[(size_t)(kk + 1) * G4H + gc]);
        w2p[j] = pk2(W2[(size_t)kk * G4H + gc], W2[(size_t)(kk + 1) * G4H + gc]);
        u2p[j] = pk2(U2[(size_t)kk * G4H + gc], U2[(size_t)(kk + 1) * G4H + gc]);
    }
    const float b2v = __ldg(b2 + gc);

    // zero staging buffers + cell states
#pragma unroll
    for (int i = 0; i < 8; i++)
        *(float4*)(ls + (tid + i * 512) * 4) = make_float4(0.f, 0.f, 0.f, 0.f);
    if (tid < 64) { c1s[tid] = 0.f; c2s[tid] = 0.f; }
    __syncthreads();

    // reduce-role identity (threads < 256: z1 for (rb, rlc); >= 256: z2)
    const int rid = tid & 255;
    const int rb = rid >> 4;
    const int rlc = rid & 15;
    const int rgc = ((rlc >> 2) << 9) + hu0 + (rlc & 3);

    for (int s = 0; s <= TT; s++) {
        float xwv = 0.f;
        if (tid < 256 && s < TT)
            xwv = __ldg(&g_xw[((size_t)s * BB + rb) * G4H + rgc]);

        // stage h1[s-1] and h2[s-2] in two b-chunks
        if (s >= 1) {
            const float* hp = g_h1b[(s - 1) & 1];
            const float* hq = g_h2b[s & 1];
#pragma unroll
            for (int i = 0; i < 2; i++) {
                int u = tid + i * 512;
                cp_async16(h1s_a + (uint32_t)u * 16u, hp + u * 4);
                if (s >= 2) cp_async16(h2s_a + (uint32_t)u * 16u, hq + u * 4);
            }
            cp_commit();
#pragma unroll
            for (int i = 2; i < 4; i++) {
                int u = tid + i * 512;
                cp_async16(h1s_a + (uint32_t)u * 16u, hp + u * 4);
                if (s >= 2) cp_async16(h2s_a + (uint32_t)u * 16u, hq + u * 4);
            }
            cp_commit();
        } else {
            cp_commit();
            cp_commit();
        }

        // compute partial dots in two b-halves, overlapped with staging
#pragma unroll
        for (int half = 0; half < 2; half++) {
            if (half == 0) cp_wait<1>(); else cp_wait<0>();
            __syncthreads();
#pragma unroll 2
            for (int bi = 0; bi < 8; bi++) {
                int b = half * 8 + bi;
                uint32_t a1 = h1s_a + (uint32_t)(b * 2048 + k0 * 4);
                uint32_t a2 = h2s_a + (uint32_t)(b * 2048 + k0 * 4);
                ull q0, q1, q2, q3, q4, q5, q6, q7;
                lds_v2u64(q0, q1, a1);
                lds_v2u64(q2, q3, a1 + 16);
                lds_v2u64(q4, q5, a1 + 32);
                lds_v2u64(q6, q7, a1 + 48);
                ull acc1 = 0, accw = 0;
                acc1 = fma2(q0, u1p[0], acc1); accw = fma2(q0, w2p[0], accw);
                acc1 = fma2(q1, u1p[1], acc1); accw = fma2(q1, w2p[1], accw);
                acc1 = fma2(q2, u1p[2], acc1); accw = fma2(q2, w2p[2], accw);
                acc1 = fma2(q3, u1p[3], acc1); accw = fma2(q3, w2p[3], accw);
                acc1 = fma2(q4, u1p[4], acc1); accw = fma2(q4, w2p[4], accw);
                acc1 = fma2(q5, u1p[5], acc1); accw = fma2(q5, w2p[5], accw);
                acc1 = fma2(q6, u1p[6], acc1); accw = fma2(q6, w2p[6], accw);
                acc1 = fma2(q7, u1p[7], acc1); accw = fma2(q7, w2p[7], accw);
                ull r0, r1, r2, r3, r4, r5, r6, r7;
                lds_v2u64(r0, r1, a2);
                lds_v2u64(r2, r3, a2 + 16);
                lds_v2u64(r4, r5, a2 + 32);
                lds_v2u64(r6, r7, a2 + 48);
                ull acc2 = 0;
                acc2 = fma2(r0, u2p[0], acc2);
                acc2 = fma2(r1, u2p[1], acc2);
                acc2 = fma2(r2, u2p[2], acc2);
                acc2 = fma2(r3, u2p[3], acc2);
                acc2 = fma2(r4, u2p[4], acc2);
                acc2 = fma2(r5, u2p[5], acc2);
                acc2 = fma2(r6, u2p[6], acc2);
                acc2 = fma2(r7, u2p[7], acc2);
                int po = b * 544 + lc * 34 + ks;
                p1[po] = sum2(acc1);
                p2[po] = sum2(accw) + sum2(acc2);
            }
        }
        __syncthreads();

        // parallel reduce: tid<256 -> z1, tid>=256 -> z2
        {
            const float* pp = (tid < 256 ? p1 : p2) + rb * 544 + rlc * 34;
            float z = (tid < 256) ? xwv : b2v;
            float za = 0.f, zb = 0.f;
#pragma unroll
            for (int i = 0; i < 8; i++) {
                float2 v0 = *(const float2*)(pp + 4 * i);
                float2 v1 = *(const float2*)(pp + 4 * i + 2);
                za += v0.x + v0.y;
                zb += v1.x + v1.y;
            }
            z += za + zb;
            if (tid < 256) zsh1[rid] = z; else zsh2[rid] = z;
        }
        __syncthreads();

        // gate writers: tid<64 layer1, 64<=tid<128 layer2
        if (tid < 64 && s < TT) {
            int bb = tid >> 2, j = tid & 3;
            float zi = zsh1[bb * 16 + j];
            float zf = zsh1[bb * 16 + 4 + j];
            float zg = zsh1[bb * 16 + 8 + j];
            float zo = zsh1[bb * 16 + 12 + j];
            float ig = 1.f / (1.f + expf(-zi));
            float fg = 1.f / (1.f + expf(-zf));
            float gg = tanhf(zg);
            float og = 1.f / (1.f + expf(-zo));
            float c = fg * c1s[tid] + ig * gg;
            c1s[tid] = c;
            g_h1b[s & 1][bb * HH + hu0 + j] = og * tanhf(c);
        } else if (tid >= 64 && tid < 128 && s >= 1) {
            int w = tid - 64;
            int bb = w >> 2, j = w & 3;
            int t = s - 1;
            float zi = zsh2[bb * 16 + j];
            float zf = zsh2[bb * 16 + 4 + j];
            float zg = zsh2[bb * 16 + 8 + j];
            float zo = zsh2[bb * 16 + 12 + j];
            float ig = 1.f / (1.f + expf(-zi));
            float fg = 1.f / (1.f + expf(-zf));
            float gg = tanhf(zg);
            float og = 1.f / (1.f + expf(-zo));
            float c = fg * c2s[w] + ig * gg;
            c2s[w] = c;
            float h = og * tanhf(c);
            g_h2b[t & 1][bb * HH + hu0 + j] = h;
            g_a_h[((size_t)t * BB + bb) * HH + hu0 + j] = __float2half(h);
        }
        grid_barrier(NCTA_LSTM);
    }
}

// ------------------------- fp16 B transpose -------------------------------------
__global__ void transB_kernel(const float* __restrict__ Wd)
{
    __shared__ __half sh[32][33];
    const int v0 = blockIdx.x * 32;
    const int h0 = blockIdx.y * 32;
    const int tx = threadIdx.x;
    const int ty = threadIdx.y;
#pragma unroll
    for (int j = 0; j < 4; j++) {
        int hr = ty + j * 8;
        sh[hr][tx] = __float2half(Wd[(size_t)(h0 + hr) * VV + v0 + tx]);
    }
    __syncthreads();
#pragma unroll
    for (int j = 0; j < 4; j++) {
        int vr = ty + j * 8;
        g_b_h[(size_t)(v0 + vr) * HH + h0 + tx] = sh[tx][vr];
    }
}

// ------------------------- HMMA dense GEMM (fp16, 3-stage pipeline) -------------
#define DARR 10240u          // bytes per sub-array (128*80)
#define DSTG 20480u          // bytes per stage (A|B)

__device__ __forceinline__ void dense_load_chunk(uint32_t sb, int m0, int n0, int c, int tid)
{
    const uint32_t stg = sb + (uint32_t)(c % 3) * DSTG;
    const int kc0 = c * 32;
#pragma unroll
    for (int it = 0; it < 4; it++) {
        int u = tid + it * 256;          // 0..1023 16B units
        int arr = u >> 9;                // 0 A, 1 B
        int u2 = u & 511;
        int r = u2 >> 2, q = u2 & 3;
        const __half* g = arr ? g_b_h : g_a_h;
        int grow = arr ? n0 : m0;
        cp_async16(stg + (uint32_t)arr * DARR + (uint32_t)(r * 80 + q * 16),
                   g + (size_t)(grow + r) * HH + kc0 + q * 8);
    }
    cp_commit();
}

__global__ __launch_bounds__(256, 2)
void dense_kernel(const float* __restrict__ bd, float* __restrict__ out)
{
    extern __shared__ char smem[];
    const uint32_t sb = smem_u32(smem);
    const int tid = threadIdx.x;
    const int wid = tid >> 5;
    const int lane = tid & 31;
    const int n0 = blockIdx.x * 128;
    const int m0 = blockIdx.y * 128;
    const int wm = wid & 1;
    const int wn = wid >> 1;
    const int lrow = lane & 15;
    const int lsel = (lane >> 4) << 4;

    float acc[4][4][4];
#pragma unroll
    for (int mt = 0; mt < 4; mt++)
#pragma unroll
        for (int nt = 0; nt < 4; nt++)
#pragma unroll
            for (int e = 0; e < 4; e++) acc[mt][nt][e] = 0.f;

    dense_load_chunk(sb, m0, n0, 0, tid);
    dense_load_chunk(sb, m0, n0, 1, tid);

    for (int c = 0; c < 16; c++) {
        if (c < 15) cp_wait<1>(); else cp_wait<0>();
        __syncthreads();
        if (c + 2 < 16) dense_load_chunk(sb, m0, n0, c + 2, tid);

        const uint32_t stg = sb + (uint32_t)(c % 3) * DSTG;
        const uint32_t a_b = stg + (uint32_t)((wm * 64 + lrow) * 80) + lsel;
        const uint32_t b_b = stg + DARR + (uint32_t)((wn * 32 + lrow) * 80) + lsel;
#pragma unroll
        for (int s = 0; s < 2; s++) {
            uint32_t bf[2][4];
#pragma unroll
            for (int i = 0; i < 2; i++)
                ldm_x4(bf[i], b_b + (uint32_t)(i * 16 * 80 + s * 32));
#pragma unroll
            for (int mt = 0; mt < 4; mt++) {
                uint32_t a[4];
                ldm_x4(a, a_b + (uint32_t)(mt * 16 * 80 + s * 32));
#pragma unroll
                for (int nt = 0; nt < 4; nt++) {
                    uint32_t b0 = bf[nt >> 1][nt & 1];
                    uint32_t b1 = bf[nt >> 1][(nt & 1) + 2];
                    mma_f16(acc[mt][nt], a, b0, b1);
                }
            }
        }
    }

    // epilogue: direct stores with [t*16+b] -> [b*256+t] row remap
    const int g = lane >> 2;
    const int tig = lane & 3;
#pragma unroll
    for (int nt = 0; nt < 4; nt++) {
        int col = n0 + wn * 32 + nt * 8 + tig * 2;
        float b0 = __ldg(bd + col);
        float b1 = __ldg(bd + col + 1);
#pragma unroll
        for (int mt = 0; mt < 4; mt++) {
            int r0 = m0 + wm * 64 + mt * 16 + g;
            int r1 = r0 + 8;
            size_t o0 = (size_t)((r0 & 15) * 256 + (r0 >> 4));
            size_t o1 = (size_t)((r1 & 15) * 256 + (r1 >> 4));
            float2 v0 = make_float2(acc[mt][nt][0] + b0, acc[mt][nt][1] + b1);
            float2 v1 = make_float2(acc[mt][nt][2] + b0, acc[mt][nt][3] + b1);
            *(float2*)(out + o0 * VV + col) = v0;
            *(float2*)(out + o1 * VV + col) = v1;
        }
    }
}

// ------------------------- launch -----------------------------------------------
extern "C" void kernel_launch(void* const* d_in, const int* in_sizes, int n_in,
                              void* d_out, int out_size)
{
    const int*   tokens = (const int*)  d_in[0];
    const float* emb    = (const float*)d_in[1];
    const float* W1     = (const float*)d_in[2];
    const float* b1     = (const float*)d_in[4];
    const float* U1     = (const float*)d_in[3];
    const float* W2     = (const float*)d_in[5];
    const float* U2     = (const float*)d_in[6];
    const float* b2     = (const float*)d_in[7];
    const float* Wd     = (const float*)d_in[8];
    const float* bd     = (const float*)d_in[9];
    float* out = (float*)d_out;

    cudaFuncSetAttribute(dense_kernel, cudaFuncAttributeMaxDynamicSharedMemorySize,
                         (int)(3 * DSTG));
    cudaFuncSetAttribute(lstm_fused_kernel, cudaFuncAttributeMaxDynamicSharedMemorySize,
                         (int)(LSM_FLOATS * sizeof(float)));

    // B transpose/convert is independent of everything else — do it first
    transB_kernel<<<dim3(VV / 32, HH / 32), dim3(32, 8)>>>(Wd);
    // 1) xw1 = gather(emb, tokens) @ W1 + b1     rows r = t*16+b
    sgemm0_kernel<<<dim3(G4H / 128, MROWS / 128), 256>>>(emb, W1, b1, tokens);
    // 2) fused dual-layer LSTM (z2 includes h1@W2+b2); writes fp16 g_a_h directly
    lstm_fused_kernel<<<NCTA_LSTM, 512, LSM_FLOATS * sizeof(float)>>>(U1, W2, U2, b2);
    // 3) logits = h2 @ Wd + bd on HMMA tensor cores (fp16 single pass)
    dense_kernel<<<dim3(VV / 128, MROWS / 128), 256, 3 * DSTG>>>(bd, out);
}